// round 1
// baseline (speedup 1.0000x reference)
#include <cuda_runtime.h>
#include <cuda_bf16.h>
#include <math.h>

// Problem constants (match reference_code)
#define CC        16          // channels
#define KK        5           // kernel size
#define LL        131072      // input length
#define PADP      2
#define STRD      2
#define L_OUT     65536       // (LL + 2*PADP - KK)/STRD + 1

#define TILE_OUT  2048
#define TILE_IN   (2 * TILE_OUT + 3)   // inputs covering [2*o0-2, 2*(o0+T-1)+2]
#define THREADS   256

__device__ __forceinline__ float tanh_approx(float x) {
    float r;
    asm("tanh.approx.f32 %0, %1;" : "=f"(r) : "f"(x));
    return r;
}

// Numerically stable logsigmoid: min(x,0) - log(1 + exp(-|x|)), all on MUFU.
__device__ __forceinline__ float log_sigmoid_fast(float x) {
    float e = __expf(-fabsf(x));
    return fminf(x, 0.0f) - __logf(1.0f + e);
}

__global__ __launch_bounds__(THREADS)
void Model_41266045780566_kernel(const float* __restrict__ x,
                                 const float* __restrict__ w,     // [C, K]
                                 const float* __restrict__ bias,  // [C]
                                 float* __restrict__ out) {
    // Even/odd split of the logsigmoid'ed input tile so window reads are
    // stride-1 in shared memory (conflict-free).
    __shared__ float s_ev[TILE_OUT + 2 + 1];  // local even indices 0..TILE_OUT+2 -> 2050? see below
    __shared__ float s_od[TILE_OUT + 2];      // local odd  indices

    const int tid  = threadIdx.x;
    const int row  = blockIdx.y;          // b*C + c
    const int c    = row & (CC - 1);      // CC = 16, power of 2
    const int o0   = blockIdx.x * TILE_OUT;
    const long long in_row_base = (long long)row * LL;

    const int in_base = 2 * o0 - PADP;    // first (unclamped) input index

    // ---- Load + transform phase: one logsigmoid per input element ----
    #pragma unroll 4
    for (int j = tid; j < TILE_IN; j += THREADS) {
        int g = in_base + j;
        g = min(max(g, 0), LL - 1);       // edge-replication pad
        float v = __ldg(&x[in_row_base + g]);
        float ls = log_sigmoid_fast(v);
        if (j & 1) s_od[j >> 1] = ls;
        else       s_ev[j >> 1] = ls;
    }

    // Per-channel weights / bias (broadcast through const/L2 path).
    const float w0 = __ldg(&w[c * KK + 0]);
    const float w1 = __ldg(&w[c * KK + 1]);
    const float w2 = __ldg(&w[c * KK + 2]);
    const float w3 = __ldg(&w[c * KK + 3]);
    const float w4 = __ldg(&w[c * KK + 4]);
    const float bc = __ldg(&bias[c]);

    __syncthreads();

    // ---- Compute phase ----
    // Output oo uses flat local inputs 2*oo + {0..4}:
    //   even: s_ev[oo], s_ev[oo+1], s_ev[oo+2]   (k = 0,2,4)
    //   odd : s_od[oo], s_od[oo+1]               (k = 1,3)
    float* __restrict__ out_row = out + (long long)row * L_OUT + o0;
    #pragma unroll 2
    for (int oo = tid; oo < TILE_OUT; oo += THREADS) {
        float acc = s_ev[oo + 2] * w4;
        acc = fmaf(s_od[oo + 1], w3, acc);
        acc = fmaf(s_ev[oo + 1], w2, acc);
        acc = fmaf(s_od[oo + 0], w1, acc);
        acc = fmaf(s_ev[oo + 0], w0, acc);
        out_row[oo] = tanh_approx(acc + bc);
    }
}

extern "C" void kernel_launch(void* const* d_in, const int* in_sizes, int n_in,
                              void* d_out, int out_size) {
    const float* x    = (const float*)d_in[0];   // [B, C, L]
    const float* w    = (const float*)d_in[1];   // [C, K]
    const float* bias = (const float*)d_in[2];   // [C]
    float* out = (float*)d_out;                  // [B, C, L_OUT]

    const int rows = in_sizes[0] / LL;           // B * C
    dim3 grid(L_OUT / TILE_OUT, rows);           // 32 x 512 blocks
    Model_41266045780566_kernel<<<grid, THREADS>>>(x, w, bias, out);
}

// round 4
// speedup vs baseline: 1.2841x; 1.2841x over previous
#include <cuda_runtime.h>
#include <cuda_bf16.h>
#include <math.h>

#define CC        16
#define KK        5
#define LL        131072
#define L_OUT     65536

#define TILE_OUT  2048
#define THREADS   256
// flat local input tile: m in [0, 4104), m = g - A, A = 2*o0 - 4 (16B aligned)
#define TILE_M    4104
#define NV4       (TILE_M / 4)   // 1026 float4s

__device__ __forceinline__ float tanh_approx(float x) {
    float r;
    asm("tanh.approx.f32 %0, %1;" : "=f"(r) : "f"(x));
    return r;
}

__device__ __forceinline__ float ex2_approx(float x) {
    float r;
    asm("ex2.approx.f32 %0, %1;" : "=f"(r) : "f"(x));
    return r;
}

__device__ __forceinline__ float lg2_approx(float x) {
    float r;
    asm("lg2.approx.f32 %0, %1;" : "=f"(r) : "f"(x));
    return r;
}

// logsigmoid(x) = min(x,0) - ln2 * lg2(1 + ex2(-|x|*log2e))  : 2 MUFU + 4 ALU/FMA
__device__ __forceinline__ float log_sigmoid_fast(float x) {
    const float LOG2E = 1.4426950408889634f;
    const float LN2   = 0.6931471805599453f;
    float e = ex2_approx(-fabsf(x) * LOG2E);
    float l = lg2_approx(1.0f + e);
    return fmaf(-LN2, l, fminf(x, 0.0f));
}

__global__ __launch_bounds__(THREADS)
void Model_41266045780566_kernel(const float* __restrict__ x,
                                 const float* __restrict__ w,     // [C, K]
                                 const float* __restrict__ bias,  // [C]
                                 float* __restrict__ out) {
    __shared__ __align__(16) float s_ev[TILE_M / 2];  // 2052
    __shared__ __align__(16) float s_od[TILE_M / 2];  // 2052

    const int tid = threadIdx.x;
    const int row = blockIdx.y;                  // b*C + c
    const int c   = row & (CC - 1);
    const int o0  = blockIdx.x * TILE_OUT;
    const long long in_row_base = (long long)row * LL;
    const int A = 2 * o0 - 4;                    // aligned tile start (multiple of 4)

    const bool boundary = (blockIdx.x == 0) | (blockIdx.x == gridDim.x - 1);

    if (!boundary) {
        // ---- Fast interior path: aligned float4 loads, no clamping ----
        const float4* __restrict__ xv =
            (const float4*)(x + in_row_base + A);
        #pragma unroll
        for (int it = 0; it < 4; ++it) {
            const int j4 = tid + it * THREADS;
            float4 v = __ldg(&xv[j4]);
            float l0 = log_sigmoid_fast(v.x);
            float l1 = log_sigmoid_fast(v.y);
            float l2 = log_sigmoid_fast(v.z);
            float l3 = log_sigmoid_fast(v.w);
            *(float2*)&s_ev[2 * j4] = make_float2(l0, l2);
            *(float2*)&s_od[2 * j4] = make_float2(l1, l3);
        }
        if (tid < NV4 - 1024) {                  // last 2 float4s
            const int j4 = 1024 + tid;
            float4 v = __ldg(&xv[j4]);
            float l0 = log_sigmoid_fast(v.x);
            float l1 = log_sigmoid_fast(v.y);
            float l2 = log_sigmoid_fast(v.z);
            float l3 = log_sigmoid_fast(v.w);
            *(float2*)&s_ev[2 * j4] = make_float2(l0, l2);
            *(float2*)&s_od[2 * j4] = make_float2(l1, l3);
        }
    } else {
        // ---- Boundary path: scalar with edge-replication clamp ----
        for (int m = tid; m < TILE_M; m += THREADS) {
            int g = A + m;
            g = min(max(g, 0), LL - 1);
            float ls = log_sigmoid_fast(__ldg(&x[in_row_base + g]));
            if (m & 1) s_od[m >> 1] = ls;
            else       s_ev[m >> 1] = ls;
        }
    }

    const float w0 = __ldg(&w[c * KK + 0]);
    const float w1 = __ldg(&w[c * KK + 1]);
    const float w2 = __ldg(&w[c * KK + 2]);
    const float w3 = __ldg(&w[c * KK + 3]);
    const float w4 = __ldg(&w[c * KK + 4]);
    const float bc = __ldg(&bias[c]);

    __syncthreads();

    // ---- Compute phase: 4 outputs per thread per iteration ----
    // Output local index p: window g = 2*(o0+p) - 2 + j  ->  m = 2p + 2 + j
    //   j=0: ev[p+1], j=1: od[p+1], j=2: ev[p+2], j=3: od[p+2], j=4: ev[p+3]
    // Quad p = 4q..4q+3 needs ev[4q+1..4q+6], od[4q+1..4q+5].
    float4* __restrict__ outv = (float4*)(out + (long long)row * L_OUT + o0);
    #pragma unroll
    for (int it = 0; it < 2; ++it) {
        const int q  = tid + it * THREADS;       // quad index 0..511
        const int oo = 4 * q;
        float4 ev_a = *(const float4*)&s_ev[oo];       // ev[4q..4q+3]
        float4 ev_b = *(const float4*)&s_ev[oo + 4];   // ev[4q+4..4q+7]
        float4 od_a = *(const float4*)&s_od[oo];       // od[4q..4q+3]
        float2 od_b = *(const float2*)&s_od[oo + 4];   // od[4q+4..4q+5]

        float a0 = fmaf(ev_a.y, w0, fmaf(od_a.y, w1, fmaf(ev_a.z, w2, fmaf(od_a.z, w3, ev_a.w * w4))));
        float a1 = fmaf(ev_a.z, w0, fmaf(od_a.z, w1, fmaf(ev_a.w, w2, fmaf(od_a.w, w3, ev_b.x * w4))));
        float a2 = fmaf(ev_a.w, w0, fmaf(od_a.w, w1, fmaf(ev_b.x, w2, fmaf(od_b.x, w3, ev_b.y * w4))));
        float a3 = fmaf(ev_b.x, w0, fmaf(od_b.x, w1, fmaf(ev_b.y, w2, fmaf(od_b.y, w3, ev_b.z * w4))));

        outv[q] = make_float4(tanh_approx(a0 + bc),
                              tanh_approx(a1 + bc),
                              tanh_approx(a2 + bc),
                              tanh_approx(a3 + bc));
    }
}

extern "C" void kernel_launch(void* const* d_in, const int* in_sizes, int n_in,
                              void* d_out, int out_size) {
    const float* x    = (const float*)d_in[0];
    const float* w    = (const float*)d_in[1];
    const float* bias = (const float*)d_in[2];
    float* out = (float*)d_out;

    const int rows = in_sizes[0] / LL;           // B * C = 512
    dim3 grid(L_OUT / TILE_OUT, rows);           // 32 x 512
    Model_41266045780566_kernel<<<grid, THREADS>>>(x, w, bias, out);
}

// round 5
// speedup vs baseline: 1.3497x; 1.0511x over previous
#include <cuda_runtime.h>
#include <cuda_bf16.h>
#include <math.h>

#define CC        16
#define KK        5
#define LL        131072
#define L_OUT     65536

#define THREADS        256
#define OUT_PER_THREAD 4
#define TILE_OUT       (THREADS * OUT_PER_THREAD)   // 1024 outputs per block

__device__ __forceinline__ float tanh_approx(float x) {
    float r;
    asm("tanh.approx.f32 %0, %1;" : "=f"(r) : "f"(x));
    return r;
}
__device__ __forceinline__ float ex2_approx(float x) {
    float r;
    asm("ex2.approx.f32 %0, %1;" : "=f"(r) : "f"(x));
    return r;
}
__device__ __forceinline__ float lg2_approx(float x) {
    float r;
    asm("lg2.approx.f32 %0, %1;" : "=f"(r) : "f"(x));
    return r;
}

// logsigmoid(x) = min(x,0) - ln2 * lg2(1 + ex2(-|x|*log2e)) : 2 MUFU + 4 FMA/ALU
__device__ __forceinline__ float log_sigmoid_fast(float x) {
    const float LOG2E = 1.4426950408889634f;
    const float LN2   = 0.6931471805599453f;
    float e = ex2_approx(-fabsf(x) * LOG2E);
    float l = lg2_approx(1.0f + e);
    return fmaf(-LN2, l, fminf(x, 0.0f));
}

__global__ __launch_bounds__(THREADS)
void Model_41266045780566_kernel(const float* __restrict__ x,
                                 const float* __restrict__ w,     // [C, K]
                                 const float* __restrict__ bias,  // [C]
                                 float* __restrict__ out) {
    const int tid  = threadIdx.x;
    const int lane = tid & 31;
    const int row  = blockIdx.y;                 // b*C + c
    const int c    = row & (CC - 1);
    const long long row_in  = (long long)row * LL;
    const long long row_out = (long long)row * L_OUT;

    // This thread's 4 outputs start at o0; its 8 owned inputs are [g0, g0+8).
    // Full window needed: inputs [g0-2, g0+8].
    const int o0 = blockIdx.x * TILE_OUT + tid * OUT_PER_THREAD;
    const int g0 = 2 * o0;                       // multiple of 8 -> 16B aligned

    const float* xp = x + row_in + g0;
    float4 v0 = __ldcs((const float4*)xp);       // g0 .. g0+3
    float4 v1 = __ldcs((const float4*)(xp + 4)); // g0+4 .. g0+7

    float ls0 = log_sigmoid_fast(v0.x);
    float ls1 = log_sigmoid_fast(v0.y);
    float ls2 = log_sigmoid_fast(v0.z);
    float ls3 = log_sigmoid_fast(v0.w);
    float ls4 = log_sigmoid_fast(v1.x);
    float ls5 = log_sigmoid_fast(v1.y);
    float ls6 = log_sigmoid_fast(v1.z);
    float ls7 = log_sigmoid_fast(v1.w);

    // Halo via warp shuffle: neighbor lanes own adjacent 8-element spans.
    const unsigned FULL = 0xffffffffu;
    float lsm2 = __shfl_up_sync(FULL, ls6, 1);   // ls of g0-2
    float lsm1 = __shfl_up_sync(FULL, ls7, 1);   // ls of g0-1
    float ls8  = __shfl_down_sync(FULL, ls0, 1); // ls of g0+8

    // Warp-edge lanes: fetch halo from global (clamped => edge-replication pad).
    if (lane == 0) {
        int gm2 = max(g0 - 2, 0);
        int gm1 = max(g0 - 1, 0);
        lsm2 = log_sigmoid_fast(__ldg(&x[row_in + gm2]));
        lsm1 = log_sigmoid_fast(__ldg(&x[row_in + gm1]));
    }
    if (lane == 31) {
        int g8 = min(g0 + 8, LL - 1);
        ls8 = log_sigmoid_fast(__ldg(&x[row_in + g8]));
    }

    const float w0 = __ldg(&w[c * KK + 0]);
    const float w1 = __ldg(&w[c * KK + 1]);
    const float w2 = __ldg(&w[c * KK + 2]);
    const float w3 = __ldg(&w[c * KK + 3]);
    const float w4 = __ldg(&w[c * KK + 4]);
    const float bc = __ldg(&bias[c]);

    // Output o uses inputs 2o-2 .. 2o+2 (k = 0..4).
    float a0 = fmaf(lsm2, w0, fmaf(lsm1, w1, fmaf(ls0, w2, fmaf(ls1, w3, ls2 * w4))));
    float a1 = fmaf(ls0,  w0, fmaf(ls1,  w1, fmaf(ls2, w2, fmaf(ls3, w3, ls4 * w4))));
    float a2 = fmaf(ls2,  w0, fmaf(ls3,  w1, fmaf(ls4, w2, fmaf(ls5, w3, ls6 * w4))));
    float a3 = fmaf(ls4,  w0, fmaf(ls5,  w1, fmaf(ls6, w2, fmaf(ls7, w3, ls8 * w4))));

    float4 r = make_float4(tanh_approx(a0 + bc),
                           tanh_approx(a1 + bc),
                           tanh_approx(a2 + bc),
                           tanh_approx(a3 + bc));
    __stcs((float4*)(out + row_out + o0), r);
}

extern "C" void kernel_launch(void* const* d_in, const int* in_sizes, int n_in,
                              void* d_out, int out_size) {
    const float* x    = (const float*)d_in[0];
    const float* w    = (const float*)d_in[1];
    const float* bias = (const float*)d_in[2];
    float* out = (float*)d_out;

    const int rows = in_sizes[0] / LL;             // B * C = 512
    dim3 grid(L_OUT / TILE_OUT, rows);             // 64 x 512
    Model_41266045780566_kernel<<<grid, THREADS>>>(x, w, bias, out);
}

// round 6
// speedup vs baseline: 1.4879x; 1.1023x over previous
#include <cuda_runtime.h>
#include <cuda_bf16.h>
#include <math.h>

#define CC        16
#define KK        5
#define LL        131072
#define L_OUT     65536

#define THREADS        256
#define OUT_PER_THREAD 8
#define TILE_OUT       (THREADS * OUT_PER_THREAD)   // 2048 outputs per block

__device__ __forceinline__ float tanh_approx(float x) {
    float r;
    asm("tanh.approx.f32 %0, %1;" : "=f"(r) : "f"(x));
    return r;
}
__device__ __forceinline__ float ex2_approx(float x) {
    float r;
    asm("ex2.approx.f32 %0, %1;" : "=f"(r) : "f"(x));
    return r;
}
__device__ __forceinline__ float lg2_approx(float x) {
    float r;
    asm("lg2.approx.f32 %0, %1;" : "=f"(r) : "f"(x));
    return r;
}

// logsigmoid(x) = min(x,0) - ln2 * lg2(1 + ex2(-|x|*log2e)) : 2 MUFU + 4 FMA/ALU
__device__ __forceinline__ float log_sigmoid_fast(float x) {
    const float LOG2E = 1.4426950408889634f;
    const float LN2   = 0.6931471805599453f;
    float e = ex2_approx(-fabsf(x) * LOG2E);
    float l = lg2_approx(1.0f + e);
    return fmaf(-LN2, l, fminf(x, 0.0f));
}

__global__ __launch_bounds__(THREADS)
void Model_41266045780566_kernel(const float* __restrict__ x,
                                 const float* __restrict__ w,     // [C, K]
                                 const float* __restrict__ bias,  // [C]
                                 float* __restrict__ out) {
    const int tid  = threadIdx.x;
    const int lane = tid & 31;
    const int row  = blockIdx.y;                 // b*C + c
    const int c    = row & (CC - 1);
    const long long row_in  = (long long)row * LL;
    const long long row_out = (long long)row * L_OUT;

    // 8 outputs starting at o0; 16 owned inputs [g0, g0+16). Window: [g0-2, g0+16].
    const int o0 = blockIdx.x * TILE_OUT + tid * OUT_PER_THREAD;
    const int g0 = 2 * o0;                       // multiple of 16 -> aligned

    // Front-batched loads for MLP.
    const float* xp = x + row_in + g0;
    float4 v0 = __ldcs((const float4*)(xp));
    float4 v1 = __ldcs((const float4*)(xp + 4));
    float4 v2 = __ldcs((const float4*)(xp + 8));
    float4 v3 = __ldcs((const float4*)(xp + 12));

    float ls0  = log_sigmoid_fast(v0.x);
    float ls1  = log_sigmoid_fast(v0.y);
    float ls2  = log_sigmoid_fast(v0.z);
    float ls3  = log_sigmoid_fast(v0.w);
    float ls4  = log_sigmoid_fast(v1.x);
    float ls5  = log_sigmoid_fast(v1.y);
    float ls6  = log_sigmoid_fast(v1.z);
    float ls7  = log_sigmoid_fast(v1.w);
    float ls8  = log_sigmoid_fast(v2.x);
    float ls9  = log_sigmoid_fast(v2.y);
    float ls10 = log_sigmoid_fast(v2.z);
    float ls11 = log_sigmoid_fast(v2.w);
    float ls12 = log_sigmoid_fast(v3.x);
    float ls13 = log_sigmoid_fast(v3.y);
    float ls14 = log_sigmoid_fast(v3.z);
    float ls15 = log_sigmoid_fast(v3.w);

    // Halo via warp shuffle (neighbor lanes own adjacent 16-element spans).
    const unsigned FULL = 0xffffffffu;
    float lsm2 = __shfl_up_sync(FULL, ls14, 1);   // ls of g0-2
    float lsm1 = __shfl_up_sync(FULL, ls15, 1);   // ls of g0-1
    float ls16 = __shfl_down_sync(FULL, ls0, 1);  // ls of g0+16

    // Warp-edge lanes: fetch halo from global (clamped => edge-replication pad).
    if (lane == 0) {
        int gm2 = max(g0 - 2, 0);
        int gm1 = max(g0 - 1, 0);
        lsm2 = log_sigmoid_fast(__ldg(&x[row_in + gm2]));
        lsm1 = log_sigmoid_fast(__ldg(&x[row_in + gm1]));
    }
    if (lane == 31) {
        int g16 = min(g0 + 16, LL - 1);
        ls16 = log_sigmoid_fast(__ldg(&x[row_in + g16]));
    }

    const float w0 = __ldg(&w[c * KK + 0]);
    const float w1 = __ldg(&w[c * KK + 1]);
    const float w2 = __ldg(&w[c * KK + 2]);
    const float w3 = __ldg(&w[c * KK + 3]);
    const float w4 = __ldg(&w[c * KK + 4]);
    const float bc = __ldg(&bias[c]);

    // Output i (local) uses ls[2i-2 .. 2i+2].
    float a0 = fmaf(lsm2, w0, fmaf(lsm1, w1, fmaf(ls0,  w2, fmaf(ls1,  w3, ls2  * w4))));
    float a1 = fmaf(ls0,  w0, fmaf(ls1,  w1, fmaf(ls2,  w2, fmaf(ls3,  w3, ls4  * w4))));
    float a2 = fmaf(ls2,  w0, fmaf(ls3,  w1, fmaf(ls4,  w2, fmaf(ls5,  w3, ls6  * w4))));
    float a3 = fmaf(ls4,  w0, fmaf(ls5,  w1, fmaf(ls6,  w2, fmaf(ls7,  w3, ls8  * w4))));
    float a4 = fmaf(ls6,  w0, fmaf(ls7,  w1, fmaf(ls8,  w2, fmaf(ls9,  w3, ls10 * w4))));
    float a5 = fmaf(ls8,  w0, fmaf(ls9,  w1, fmaf(ls10, w2, fmaf(ls11, w3, ls12 * w4))));
    float a6 = fmaf(ls10, w0, fmaf(ls11, w1, fmaf(ls12, w2, fmaf(ls13, w3, ls14 * w4))));
    float a7 = fmaf(ls12, w0, fmaf(ls13, w1, fmaf(ls14, w2, fmaf(ls15, w3, ls16 * w4))));

    float4 r0 = make_float4(tanh_approx(a0 + bc), tanh_approx(a1 + bc),
                            tanh_approx(a2 + bc), tanh_approx(a3 + bc));
    float4 r1 = make_float4(tanh_approx(a4 + bc), tanh_approx(a5 + bc),
                            tanh_approx(a6 + bc), tanh_approx(a7 + bc));
    float* op = out + row_out + o0;
    __stcs((float4*)op, r0);
    __stcs((float4*)(op + 4), r1);
}

extern "C" void kernel_launch(void* const* d_in, const int* in_sizes, int n_in,
                              void* d_out, int out_size) {
    const float* x    = (const float*)d_in[0];
    const float* w    = (const float*)d_in[1];
    const float* bias = (const float*)d_in[2];
    float* out = (float*)d_out;

    const int rows = in_sizes[0] / LL;             // B * C = 512
    dim3 grid(L_OUT / TILE_OUT, rows);             // 32 x 512
    Model_41266045780566_kernel<<<grid, THREADS>>>(x, w, bias, out);
}